// round 1
// baseline (speedup 1.0000x reference)
#include <cuda_runtime.h>
#include <cstdint>

#define B_WIN   4096
#define NTOK    49
#define DIMC    384
#define NH      12
#define HD      32
#define M_TOTAL (B_WIN * NTOK)     // 200704
#define KDIM    384
#define QK_SCALE 0.17677669529663687f   // 1/sqrt(32)

// ---------------- scratch (no cudaMalloc allowed) ----------------
__device__ float g_qkv[(size_t)M_TOTAL * 1152];   // ~925 MB
__device__ float g_att[(size_t)M_TOTAL * DIMC];   // ~308 MB
__device__ float g_bias[NH * NTOK * NTOK];        // 115 KB expanded rel-pos bias

// ---------------- helpers ----------------
__device__ __forceinline__ uint32_t f2tf(float f) {
    uint32_t r;
    asm("cvt.rna.tf32.f32 %0, %1;" : "=r"(r) : "f"(f));
    return r;
}

// ---------------- bias expansion: g_bias[h][i][j] = bias_table[rel_index[i][j]][h] ----------------
__global__ void bias_expand_kernel(const float* __restrict__ bt, const int* __restrict__ ri) {
    int h = blockIdx.x;
    for (int e = threadIdx.x; e < NTOK * NTOK; e += blockDim.x)
        g_bias[h * NTOK * NTOK + e] = bt[ri[e] * NH + h];
}

// ---------------- tf32 tensor-core GEMM: C[M,Nc] = A[M,K] @ W[Nc,K]^T + bias ----------------
// BM=128, BN=32, BK=32, 256 threads = 8 warps, each warp owns a 16x32 output strip.
// mode 0: A = Aext (x),  C = g_qkv     (QKV projection, Nc=1152)
// mode 1: A = g_att,     C = Cext(out) (output projection, Nc=384)
#define BM  128
#define BN  32
#define BK  32
#define LDP 36   // smem row pitch (floats); pad 4 -> conflict-free fragment LDS

__global__ __launch_bounds__(256, 1) void gemm_tf32_kernel(
    const float* __restrict__ Aext, const float* __restrict__ W,
    const float* __restrict__ bias, float* __restrict__ Cext,
    int Nc, int mode)
{
    const float* A = (mode == 0) ? Aext : g_att;
    float*       C = (mode == 0) ? g_qkv : Cext;

    __shared__ uint32_t As[2][BM * LDP];
    __shared__ uint32_t Bs[2][BN * LDP];

    const int tid  = threadIdx.x;
    const int warp = tid >> 5;
    const int lane = tid & 31;
    const int g    = lane >> 2;   // group id (0..7)
    const int tg   = lane & 3;    // thread-in-group (0..3)

    const size_t mbase = (size_t)blockIdx.x * BM;
    const size_t nbase = (size_t)blockIdx.y * BN;
    const int KT = KDIM / BK;     // 12

    uint32_t a_st[4][4];          // staged A: 4 float4 per thread
    uint32_t b_st[4];             // staged B: 1 float4 per thread

    float acc[4][4];
#pragma unroll
    for (int f = 0; f < 4; f++)
#pragma unroll
        for (int i = 0; i < 4; i++) acc[f][i] = 0.f;

    auto loadAB = [&](int t) {
#pragma unroll
        for (int i = 0; i < 4; i++) {
            int idx = tid + i * 256;
            int row = idx >> 3, c4 = idx & 7;
            float4 v = *(const float4*)(A + (mbase + row) * KDIM + t * BK + c4 * 4);
            a_st[i][0] = f2tf(v.x); a_st[i][1] = f2tf(v.y);
            a_st[i][2] = f2tf(v.z); a_st[i][3] = f2tf(v.w);
        }
        {
            int row = tid >> 3, c4 = tid & 7;
            float4 v = *(const float4*)(W + (nbase + row) * KDIM + t * BK + c4 * 4);
            b_st[0] = f2tf(v.x); b_st[1] = f2tf(v.y);
            b_st[2] = f2tf(v.z); b_st[3] = f2tf(v.w);
        }
    };

    auto storeAB = [&](int buf) {
#pragma unroll
        for (int i = 0; i < 4; i++) {
            int idx = tid + i * 256;
            int row = idx >> 3, c4 = idx & 7;
            *(uint4*)&As[buf][row * LDP + c4 * 4] =
                make_uint4(a_st[i][0], a_st[i][1], a_st[i][2], a_st[i][3]);
        }
        {
            int row = tid >> 3, c4 = tid & 7;
            *(uint4*)&Bs[buf][row * LDP + c4 * 4] =
                make_uint4(b_st[0], b_st[1], b_st[2], b_st[3]);
        }
    };

    auto compute = [&](int cur) {
        const int ar = warp * 16 + g;
#pragma unroll
        for (int ks = 0; ks < 4; ks++) {
            const int kc = ks * 8 + tg;
            uint32_t a0 = As[cur][ar * LDP + kc];
            uint32_t a1 = As[cur][(ar + 8) * LDP + kc];
            uint32_t a2 = As[cur][ar * LDP + kc + 4];
            uint32_t a3 = As[cur][(ar + 8) * LDP + kc + 4];
#pragma unroll
            for (int f = 0; f < 4; f++) {
                const int bn = f * 8 + g;
                uint32_t b0 = Bs[cur][bn * LDP + kc];
                uint32_t b1 = Bs[cur][bn * LDP + kc + 4];
                asm volatile(
                    "mma.sync.aligned.m16n8k8.row.col.f32.tf32.tf32.f32 "
                    "{%0,%1,%2,%3}, {%4,%5,%6,%7}, {%8,%9}, {%0,%1,%2,%3};\n"
                    : "+f"(acc[f][0]), "+f"(acc[f][1]), "+f"(acc[f][2]), "+f"(acc[f][3])
                    : "r"(a0), "r"(a1), "r"(a2), "r"(a3), "r"(b0), "r"(b1));
            }
        }
    };

    loadAB(0);
    storeAB(0);
    __syncthreads();

#pragma unroll 1
    for (int t = 0; t < KT; t++) {
        if (t + 1 < KT) loadAB(t + 1);
        compute(t & 1);
        __syncthreads();
        if (t + 1 < KT) {
            storeAB((t + 1) & 1);
            __syncthreads();
        }
    }

    // epilogue: acc[f][{0,1}] -> (row, col..col+1), acc[f][{2,3}] -> (row+8, ...)
#pragma unroll
    for (int f = 0; f < 4; f++) {
        size_t col = nbase + f * 8 + tg * 2;
        size_t r0  = mbase + warp * 16 + g;
        float bb0 = bias[col], bb1 = bias[col + 1];
        *(float2*)&C[r0 * (size_t)Nc + col] =
            make_float2(acc[f][0] + bb0, acc[f][1] + bb1);
        *(float2*)&C[(r0 + 8) * (size_t)Nc + col] =
            make_float2(acc[f][2] + bb0, acc[f][3] + bb1);
    }
}

// ---------------- per-(window, head) attention ----------------
// One CTA per (b, h): 64 threads; threads 0..48 each own one query row.
__global__ __launch_bounds__(64, 1) void attn_kernel()
{
    __shared__ float k_s[NTOK][HD];
    __shared__ float v_s[NTOK][HD];
    __shared__ float b_s[NTOK * NTOK];

    const int bid = blockIdx.x;
    const int b = bid / NH, h = bid % NH;
    const float* base = g_qkv + (size_t)b * NTOK * 1152;
    const int tid = threadIdx.x;

    // cooperative loads: K, V tiles (float4), bias tile
    for (int idx = tid; idx < NTOK * 8; idx += 64) {
        int j = idx >> 3, dd = idx & 7;
        const float4* kp = (const float4*)(base + (size_t)j * 1152 + 384 + h * HD);
        *((float4*)&k_s[j][dd * 4]) = kp[dd];
        const float4* vp = (const float4*)(base + (size_t)j * 1152 + 768 + h * HD);
        *((float4*)&v_s[j][dd * 4]) = vp[dd];
    }
    const float* gb = g_bias + h * (NTOK * NTOK);
    for (int e = tid; e < NTOK * NTOK; e += 64) b_s[e] = gb[e];
    __syncthreads();

    if (tid < NTOK) {
        float q[HD];
        const float4* qp = (const float4*)(base + (size_t)tid * 1152 + h * HD);
#pragma unroll
        for (int d4 = 0; d4 < 8; d4++) {
            float4 t = qp[d4];
            q[d4 * 4 + 0] = t.x; q[d4 * 4 + 1] = t.y;
            q[d4 * 4 + 2] = t.z; q[d4 * 4 + 3] = t.w;
        }

        float s[NTOK];
        float mx = -1e30f;
#pragma unroll
        for (int j = 0; j < NTOK; j++) {
            float acc = 0.f;
            const float4* kr = (const float4*)&k_s[j][0];
#pragma unroll
            for (int d4 = 0; d4 < 8; d4++) {
                float4 kv = kr[d4];
                acc += q[d4 * 4 + 0] * kv.x + q[d4 * 4 + 1] * kv.y
                     + q[d4 * 4 + 2] * kv.z + q[d4 * 4 + 3] * kv.w;
            }
            float val = acc * QK_SCALE + b_s[tid * NTOK + j];
            s[j] = val;
            mx = fmaxf(mx, val);
        }

        float sum = 0.f;
#pragma unroll
        for (int j = 0; j < NTOK; j++) {
            float e = __expf(s[j] - mx);
            s[j] = e;
            sum += e;
        }
        float inv = 1.f / sum;

        float o[HD];
#pragma unroll
        for (int d = 0; d < HD; d++) o[d] = 0.f;
#pragma unroll
        for (int j = 0; j < NTOK; j++) {
            float p = s[j];
            const float4* vr = (const float4*)&v_s[j][0];
#pragma unroll
            for (int d4 = 0; d4 < 8; d4++) {
                float4 vv = vr[d4];
                o[d4 * 4 + 0] += p * vv.x; o[d4 * 4 + 1] += p * vv.y;
                o[d4 * 4 + 2] += p * vv.z; o[d4 * 4 + 3] += p * vv.w;
            }
        }

        float* op = g_att + ((size_t)b * NTOK + tid) * DIMC + h * HD;
#pragma unroll
        for (int d4 = 0; d4 < 8; d4++)
            *((float4*)&op[d4 * 4]) = make_float4(
                o[d4 * 4 + 0] * inv, o[d4 * 4 + 1] * inv,
                o[d4 * 4 + 2] * inv, o[d4 * 4 + 3] * inv);
    }
}

// ---------------- launch ----------------
extern "C" void kernel_launch(void* const* d_in, const int* in_sizes, int n_in,
                              void* d_out, int out_size)
{
    const float* x      = (const float*)d_in[0];
    const float* qkv_w  = (const float*)d_in[1];
    const float* qkv_b  = (const float*)d_in[2];
    const float* proj_w = (const float*)d_in[3];
    const float* proj_b = (const float*)d_in[4];
    const float* bt     = (const float*)d_in[5];
    const int*   ri     = (const int*)d_in[6];
    float* out = (float*)d_out;

    bias_expand_kernel<<<NH, 256>>>(bt, ri);

    dim3 gq(M_TOTAL / BM, 1152 / BN);           // 1568 x 36
    gemm_tf32_kernel<<<gq, 256>>>(x, qkv_w, qkv_b, out, 1152, 0);

    attn_kernel<<<B_WIN * NH, 64>>>();          // 49152 CTAs

    dim3 gp(M_TOTAL / BM, DIMC / BN);           // 1568 x 12
    gemm_tf32_kernel<<<gp, 256>>>(x, proj_w, proj_b, out, DIMC, 1);
}

// round 2
// speedup vs baseline: 1.6715x; 1.6715x over previous
#include <cuda_runtime.h>
#include <cstdint>

#define B_WIN   4096
#define NTOK    49
#define DIMC    384
#define NH      12
#define HD      32
#define M_TOTAL (B_WIN * NTOK)     // 200704
#define KDIM    384
#define QK_SCALE 0.17677669529663687f   // 1/sqrt(32)

// ---------------- scratch (no cudaMalloc allowed) ----------------
__device__ float g_qkv[(size_t)M_TOTAL * 1152];   // ~925 MB
__device__ float g_att[(size_t)M_TOTAL * DIMC];   // ~308 MB
__device__ float g_bias[NH * NTOK * NTOK];        // 115 KB expanded rel-pos bias

// ---------------- helpers ----------------
__device__ __forceinline__ uint32_t f2tf(float f) {
    uint32_t r;
    asm("cvt.rna.tf32.f32 %0, %1;" : "=r"(r) : "f"(f));
    return r;
}
__device__ __forceinline__ void cpa16(float* smem, const float* g) {
    uint32_t s = (uint32_t)__cvta_generic_to_shared(smem);
    asm volatile("cp.async.cg.shared.global [%0], [%1], 16;\n" :: "r"(s), "l"(g));
}

// ---------------- bias expansion ----------------
__global__ void bias_expand_kernel(const float* __restrict__ bt, const int* __restrict__ ri) {
    int h = blockIdx.x;
    for (int e = threadIdx.x; e < NTOK * NTOK; e += blockDim.x)
        g_bias[h * NTOK * NTOK + e] = bt[ri[e] * NH + h];
}

// ---------------- tf32 tensor-core GEMM: C[M,Nc] = A[M,K] @ W[Nc,K]^T + bias ----------------
// BM=128, BN=64, BK=32, 256 threads (8 warps, 4x2), warp tile 32x32.
// cp.async double-buffered, XOR-swizzled smem (48KB static), 1 barrier per k-tile.
// grid = (Nc/BN, M/BM): x = n-block so same-A CTAs run in one wave -> A hits L2.
#define BM  128
#define BN  64
#define BK  32

// XOR swizzle: 16B chunk c4 of row r stored at chunk (c4 ^ (r&7))
__device__ __forceinline__ int sw_store(int row, int c4) {
    return row * 32 + ((c4 ^ (row & 7)) << 2);
}
__device__ __forceinline__ float sw_load(const float* buf, int row, int kc) {
    return buf[row * 32 + ((((kc >> 2)) ^ (row & 7)) << 2) + (kc & 3)];
}

__global__ __launch_bounds__(256) void gemm_tf32_kernel(
    const float* __restrict__ Aext, const float* __restrict__ W,
    const float* __restrict__ bias, float* __restrict__ Cext,
    int Nc, int mode)
{
    const float* A = (mode == 0) ? Aext : g_att;
    float*       C = (mode == 0) ? g_qkv : Cext;

    __shared__ float As[2][BM * 32];   // 2 x 16KB
    __shared__ float Bs[2][BN * 32];   // 2 x 8KB   -> 48KB total

    const int tid    = threadIdx.x;
    const int warp   = tid >> 5;
    const int lane   = tid & 31;
    const int g      = lane >> 2;
    const int tg     = lane & 3;
    const int warp_m = warp >> 1;      // 0..3
    const int warp_n = warp & 1;       // 0..1

    const size_t mbase = (size_t)blockIdx.y * BM;
    const size_t nbase = (size_t)blockIdx.x * BN;
    const int KT = KDIM / BK;          // 12

    const int lrow = tid >> 3;         // 0..31
    const int lc4  = tid & 7;          // 16B chunk within 32-float row

    float acc[2][4][4];
#pragma unroll
    for (int ma = 0; ma < 2; ma++)
#pragma unroll
        for (int na = 0; na < 4; na++)
#pragma unroll
            for (int i = 0; i < 4; i++) acc[ma][na][i] = 0.f;

    auto issue = [&](int t, int buf) {
        const float* Ag = A + (mbase + lrow) * KDIM + t * BK + lc4 * 4;
#pragma unroll
        for (int i = 0; i < 4; i++)
            cpa16(&As[buf][sw_store(lrow + i * 32, lc4)], Ag + (size_t)i * 32 * KDIM);
        const float* Wg = W + (nbase + lrow) * KDIM + t * BK + lc4 * 4;
#pragma unroll
        for (int i = 0; i < 2; i++)
            cpa16(&Bs[buf][sw_store(lrow + i * 32, lc4)], Wg + (size_t)i * 32 * KDIM);
        asm volatile("cp.async.commit_group;\n");
    };

    auto compute = [&](int cur) {
        const float* Ab = As[cur];
        const float* Bb = Bs[cur];
#pragma unroll
        for (int ks = 0; ks < 4; ks++) {
            const int kc = ks * 8 + tg;
            uint32_t a[2][4];
#pragma unroll
            for (int ma = 0; ma < 2; ma++) {
                const int r = warp_m * 32 + ma * 16 + g;
                a[ma][0] = f2tf(sw_load(Ab, r,     kc));
                a[ma][1] = f2tf(sw_load(Ab, r + 8, kc));
                a[ma][2] = f2tf(sw_load(Ab, r,     kc + 4));
                a[ma][3] = f2tf(sw_load(Ab, r + 8, kc + 4));
            }
#pragma unroll
            for (int na = 0; na < 4; na++) {
                const int rb = warp_n * 32 + na * 8 + g;
                uint32_t b0 = f2tf(sw_load(Bb, rb, kc));
                uint32_t b1 = f2tf(sw_load(Bb, rb, kc + 4));
#pragma unroll
                for (int ma = 0; ma < 2; ma++) {
                    asm volatile(
                        "mma.sync.aligned.m16n8k8.row.col.f32.tf32.tf32.f32 "
                        "{%0,%1,%2,%3}, {%4,%5,%6,%7}, {%8,%9}, {%0,%1,%2,%3};\n"
                        : "+f"(acc[ma][na][0]), "+f"(acc[ma][na][1]),
                          "+f"(acc[ma][na][2]), "+f"(acc[ma][na][3])
                        : "r"(a[ma][0]), "r"(a[ma][1]), "r"(a[ma][2]), "r"(a[ma][3]),
                          "r"(b0), "r"(b1));
                }
            }
        }
    };

    issue(0, 0);
#pragma unroll 1
    for (int t = 0; t < KT; t++) {
        asm volatile("cp.async.wait_group 0;\n" ::: "memory");
        __syncthreads();
        if (t + 1 < KT) issue(t + 1, (t + 1) & 1);
        compute(t & 1);
    }

    // epilogue
#pragma unroll
    for (int ma = 0; ma < 2; ma++) {
        const size_t r0 = mbase + warp_m * 32 + ma * 16 + g;
#pragma unroll
        for (int na = 0; na < 4; na++) {
            const size_t col = nbase + warp_n * 32 + na * 8 + tg * 2;
            float b0 = __ldg(&bias[col]), b1 = __ldg(&bias[col + 1]);
            *(float2*)&C[r0 * (size_t)Nc + col] =
                make_float2(acc[ma][na][0] + b0, acc[ma][na][1] + b1);
            *(float2*)&C[(r0 + 8) * (size_t)Nc + col] =
                make_float2(acc[ma][na][2] + b0, acc[ma][na][3] + b1);
        }
    }
}

// ---------------- per-(window, head) attention ----------------
__global__ __launch_bounds__(64) void attn_kernel()
{
    __shared__ float k_s[NTOK][HD];
    __shared__ float v_s[NTOK][HD];
    __shared__ float b_s[NTOK * NTOK];

    const int bid = blockIdx.x;
    const int b = bid / NH, h = bid % NH;
    const float* base = g_qkv + (size_t)b * NTOK * 1152;
    const int tid = threadIdx.x;

    for (int idx = tid; idx < NTOK * 8; idx += 64) {
        int j = idx >> 3, dd = idx & 7;
        const float4* kp = (const float4*)(base + (size_t)j * 1152 + 384 + h * HD);
        *((float4*)&k_s[j][dd * 4]) = kp[dd];
        const float4* vp = (const float4*)(base + (size_t)j * 1152 + 768 + h * HD);
        *((float4*)&v_s[j][dd * 4]) = vp[dd];
    }
    const float* gb = g_bias + h * (NTOK * NTOK);
    for (int e = tid; e < NTOK * NTOK; e += 64) b_s[e] = gb[e];
    __syncthreads();

    if (tid < NTOK) {
        float q[HD];
        const float4* qp = (const float4*)(base + (size_t)tid * 1152 + h * HD);
#pragma unroll
        for (int d4 = 0; d4 < 8; d4++) {
            float4 t = qp[d4];
            q[d4 * 4 + 0] = t.x; q[d4 * 4 + 1] = t.y;
            q[d4 * 4 + 2] = t.z; q[d4 * 4 + 3] = t.w;
        }

        float s[NTOK];
        float mx = -1e30f;
#pragma unroll
        for (int j = 0; j < NTOK; j++) {
            float acc = 0.f;
            const float4* kr = (const float4*)&k_s[j][0];
#pragma unroll
            for (int d4 = 0; d4 < 8; d4++) {
                float4 kv = kr[d4];
                acc += q[d4 * 4 + 0] * kv.x + q[d4 * 4 + 1] * kv.y
                     + q[d4 * 4 + 2] * kv.z + q[d4 * 4 + 3] * kv.w;
            }
            float val = acc * QK_SCALE + b_s[tid * NTOK + j];
            s[j] = val;
            mx = fmaxf(mx, val);
        }

        float sum = 0.f;
#pragma unroll
        for (int j = 0; j < NTOK; j++) {
            float e = __expf(s[j] - mx);
            s[j] = e;
            sum += e;
        }
        float inv = 1.f / sum;

        float o[HD];
#pragma unroll
        for (int d = 0; d < HD; d++) o[d] = 0.f;
#pragma unroll
        for (int j = 0; j < NTOK; j++) {
            float p = s[j];
            const float4* vr = (const float4*)&v_s[j][0];
#pragma unroll
            for (int d4 = 0; d4 < 8; d4++) {
                float4 vv = vr[d4];
                o[d4 * 4 + 0] += p * vv.x; o[d4 * 4 + 1] += p * vv.y;
                o[d4 * 4 + 2] += p * vv.z; o[d4 * 4 + 3] += p * vv.w;
            }
        }

        float* op = g_att + ((size_t)b * NTOK + tid) * DIMC + h * HD;
#pragma unroll
        for (int d4 = 0; d4 < 8; d4++)
            *((float4*)&op[d4 * 4]) = make_float4(
                o[d4 * 4 + 0] * inv, o[d4 * 4 + 1] * inv,
                o[d4 * 4 + 2] * inv, o[d4 * 4 + 3] * inv);
    }
}

// ---------------- launch ----------------
extern "C" void kernel_launch(void* const* d_in, const int* in_sizes, int n_in,
                              void* d_out, int out_size)
{
    const float* x      = (const float*)d_in[0];
    const float* qkv_w  = (const float*)d_in[1];
    const float* qkv_b  = (const float*)d_in[2];
    const float* proj_w = (const float*)d_in[3];
    const float* proj_b = (const float*)d_in[4];
    const float* bt     = (const float*)d_in[5];
    const int*   ri     = (const int*)d_in[6];
    float* out = (float*)d_out;

    bias_expand_kernel<<<NH, 256>>>(bt, ri);

    dim3 gq(1152 / BN, M_TOTAL / BM);            // 18 x 1568 (x = n-block for L2 reuse)
    gemm_tf32_kernel<<<gq, 256>>>(x, qkv_w, qkv_b, out, 1152, 0);

    attn_kernel<<<B_WIN * NH, 64>>>();           // 49152 CTAs

    dim3 gp(DIMC / BN, M_TOTAL / BM);            // 6 x 1568
    gemm_tf32_kernel<<<gp, 256>>>(x, proj_w, proj_b, out, DIMC, 1);
}